// round 15
// baseline (speedup 1.0000x reference)
#include <cuda_runtime.h>
#include <math.h>

#define NN 2048
#define BB 8

// ---------------- scratch (static device allocations) ----------------
__device__ float g_PL[BB * 15 * NN];                 // left projections  [b][ct][row]
__device__ float g_PR[BB * 15 * NN];                 // right projections [b][ct][col]
__device__ float g_LR[BB * 2 * NN];                  // sigmoid outputs: [b][0]=left, [b][1]=right
__device__ float g_dsum[64 * BB];                    // per-(d,b) band sums

// ---------------- packed f32x2 helpers ----------------
__device__ __forceinline__ unsigned long long pack2(float lo, float hi) {
    unsigned long long r;
    asm("mov.b64 %0, {%1, %2};" : "=l"(r) : "f"(lo), "f"(hi));
    return r;
}
__device__ __forceinline__ void fma2(unsigned long long& d, unsigned long long a,
                                     unsigned long long b) {
    asm("fma.rn.f32x2 %0, %1, %2, %0;" : "+l"(d) : "l"(a), "l"(b));
}
__device__ __forceinline__ float hadd2(unsigned long long v) {
    float lo, hi;
    asm("mov.b64 {%0, %1}, %2;" : "=f"(lo), "=f"(hi) : "l"(v));
    return lo + hi;
}
__device__ __forceinline__ float2 unpk(unsigned long long v) {
    float lo, hi;
    asm("mov.b64 {%0, %1}, %2;" : "=f"(lo), "=f"(hi) : "l"(v));
    return make_float2(lo, hi);
}

// ---------------- dummy kernels (profiler slot alignment) ----------------
__global__ void dummy_kernel() {}

// ---------------- fused projection kernel (occupancy-4, reg-capped) ----------------
// 1280 blocks: t%5==0 -> PR block (256 total), else PL block (1024 total).
__global__ __launch_bounds__(256, 4) void proj_kernel(const float* __restrict__ x,
                                                      const float* __restrict__ wl,
                                                      const float* __restrict__ wr) {
    __shared__ __align__(16) char smem_raw[23040];
    int tid = threadIdx.x;
    int t = blockIdx.x;

    if (t % 5 == 0) {
        // ================= PR path (single-buffer staging, low regs) =================
        int pr_idx = t / 5;                                         // 0..255
        unsigned long long (*ws)[32][15] =
            (unsigned long long(*)[32][15])smem_raw;                // 15360 B
        float2 (*racc)[64][15] = (float2(*)[64][15])smem_raw;       // 23040 B, post-loop alias

        int b = pr_idx >> 5;
        int stripe = pr_idx & 31;
        int colloc = tid & 63;
        int seg = tid >> 6;                  // 0..3
        int col = stripe * 64 + colloc;
        const float* xb = x + (size_t)b * NN * NN + col;

        unsigned long long acc[15];
#pragma unroll
        for (int ct = 0; ct < 15; ++ct) acc[ct] = 0ull;

#pragma unroll 1
        for (int chunk = 0; chunk < 8; ++chunk) {
            __syncthreads();
            for (int i = tid; i < 1920; i += 256) {
                int s = i / 480, rem = i % 480;
                int hp = rem / 15, ct = rem % 15;
                int h = s * 512 + chunk * 64 + hp * 2;
                int c = ct / 3, tt = ct % 3;
                ws[s][hp][ct] = pack2(wr[((size_t)c * NN + h) * 3 + tt],
                                      wr[((size_t)c * NN + h + 1) * 3 + tt]);
            }
            __syncthreads();
            int hbase = seg * 512 + chunk * 64;
            const float* xp = xb + (size_t)hbase * NN;
#pragma unroll 4
            for (int hp = 0; hp < 32; ++hp) {
                float x0 = __ldcs(xp + (size_t)(2 * hp) * NN);
                float x1 = __ldcs(xp + (size_t)(2 * hp + 1) * NN);
                unsigned long long xv = pack2(x0, x1);
#pragma unroll
                for (int ct = 0; ct < 15; ++ct) fma2(acc[ct], xv, ws[seg][hp][ct]);
            }
        }

        __syncthreads();   // all ws reads done; safe to alias racc
        if (seg > 0) {
#pragma unroll
            for (int ct = 0; ct < 15; ++ct) racc[seg - 1][colloc][ct] = unpk(acc[ct]);
        }
        __syncthreads();
        if (seg == 0) {
#pragma unroll
            for (int ct = 0; ct < 15; ++ct) {
                float v = hadd2(acc[ct]);
#pragma unroll
                for (int s = 0; s < 3; ++s) {
                    float2 r = racc[s][colloc][ct];
                    v += r.x + r.y;
                }
                g_PR[((size_t)b * 15 + ct) * NN + col] = v;
            }
        }
    } else {
        // ================= PL path (2 rows/warp, double-buffered weights) =================
        int pl_idx = (t / 5) * 4 + (t % 5) - 1;                     // 0..1023
        float4 (*sw)[480] = (float4(*)[480])smem_raw;               // 2 x 7680 B

        int warp = tid >> 5, lane = tid & 31;
        int g = pl_idx * 8 + warp;           // 0..8191
        int b = g >> 10;
        int r0 = (g & 1023) << 1;            // 2 rows per warp
        const float* xb = x + (size_t)b * NN * NN + (size_t)r0 * NN;
        const float4* wl4 = (const float4*)wl;   // [ct][512] float4

        float acc[2][15];
#pragma unroll
        for (int r = 0; r < 2; r++)
#pragma unroll
            for (int c = 0; c < 15; c++) acc[r][c] = 0.f;

        for (int i = tid; i < 480; i += 256) {
            int ct = i >> 5, j = i & 31;
            sw[0][ct * 32 + j] = wl4[ct * 512 + j];
        }
        __syncthreads();

#pragma unroll 1
        for (int k = 0; k < 16; ++k) {
            int buf = k & 1;
            if (k < 15) {
                for (int i = tid; i < 480; i += 256) {
                    int ct = i >> 5, j = i & 31;
                    sw[buf ^ 1][ct * 32 + j] = wl4[ct * 512 + (k + 1) * 32 + j];
                }
            }
            int w = k * 128 + lane * 4;
            float4 xv0 = __ldcs((const float4*)(xb + 0 * NN + w));
            float4 xv1 = __ldcs((const float4*)(xb + 1 * NN + w));
#pragma unroll
            for (int ct = 0; ct < 15; ++ct) {
                float4 wv = sw[buf][ct * 32 + lane];
                acc[0][ct] = fmaf(xv0.x, wv.x, acc[0][ct]);
                acc[0][ct] = fmaf(xv0.y, wv.y, acc[0][ct]);
                acc[0][ct] = fmaf(xv0.z, wv.z, acc[0][ct]);
                acc[0][ct] = fmaf(xv0.w, wv.w, acc[0][ct]);
                acc[1][ct] = fmaf(xv1.x, wv.x, acc[1][ct]);
                acc[1][ct] = fmaf(xv1.y, wv.y, acc[1][ct]);
                acc[1][ct] = fmaf(xv1.z, wv.z, acc[1][ct]);
                acc[1][ct] = fmaf(xv1.w, wv.w, acc[1][ct]);
            }
            __syncthreads();
        }

#pragma unroll
        for (int r = 0; r < 2; r++) {
#pragma unroll
            for (int ct = 0; ct < 15; ++ct) {
                float v = acc[r][ct];
                v += __shfl_down_sync(0xffffffffu, v, 16);
                v += __shfl_down_sync(0xffffffffu, v, 8);
                v += __shfl_down_sync(0xffffffffu, v, 4);
                v += __shfl_down_sync(0xffffffffu, v, 2);
                v += __shfl_down_sync(0xffffffffu, v, 1);
                if (lane == 0) g_PL[((size_t)b * 15 + ct) * NN + r0 + r] = v;
            }
        }
    }
}

// ---------------- kernel 4: fused conv stack + sigmoid ----------------
#define TW 64
#define NT (NN / TW)          // 32 tiles
#define HALO 6
#define W2 (TW + 2 * HALO)    // 76
__global__ __launch_bounds__(256) void conv_kernel(
    const float* __restrict__ bl, const float* __restrict__ br,
    const float* __restrict__ wA, const float* __restrict__ bA,
    const float* __restrict__ wB, const float* __restrict__ bB,
    const float* __restrict__ wT, const float* __restrict__ bT,
    const float* __restrict__ wm, const float* __restrict__ bm) {
    __shared__ float hbuf[2][10][W2];
    __shared__ float sA[300], sB[300], sT[300];
    __shared__ float swm[20], sbA[10], sbB[10], sbT[10], sbm[2];

    int tid = threadIdx.x;
    int b = blockIdx.x / NT;
    int p0 = (blockIdx.x % NT) * TW;

    for (int i = tid; i < 300; i += 256) {
        sA[i] = wA[i];
        sB[i] = wB[i];
        int o = i / 30, ii = (i / 3) % 10, t = i % 3;
        sT[i] = wT[(ii * 10 + o) * 3 + (2 - t)];   // wTc[o][ii][t] = wT[ii][o][2-t]
    }
    if (tid < 20) swm[tid] = wm[tid];
    if (tid < 10) { sbA[tid] = bA[tid]; sbB[tid] = bB[tid]; sbT[tid] = bT[tid]; }
    if (tid < 2) sbm[tid] = bm[tid];

    // build lr (with halo) from projections + 3-tap shift + bias
    for (int i = tid; i < 10 * W2; i += 256) {
        int ch = i / W2, pl = i % W2;
        int gp = p0 - HALO + pl;
        float v = 0.f;
        if (gp >= 0 && gp < NN) {
            if (ch < 5) {
                v = bl[ch];
#pragma unroll
                for (int t = 0; t < 3; t++) {
                    int ri = gp - 1 + t;
                    if (ri >= 0 && ri < NN) v += g_PL[((size_t)b * 15 + ch * 3 + t) * NN + ri];
                }
            } else {
                int c = ch - 5;
                v = br[c];
#pragma unroll
                for (int t = 0; t < 3; t++) {
                    int ci = gp - 1 + t;
                    if (ci >= 0 && ci < NN) v += g_PR[((size_t)b * 15 + c * 3 + t) * NN + ci];
                }
            }
        }
        hbuf[0][ch][pl] = v;
    }
    __syncthreads();

    int src = 0;
#pragma unroll 1
    for (int layer = 0; layer < 6; ++layer) {
        const float* W = (layer == 0) ? sA : ((layer < 3) ? sB : sT);
        const float* bias = (layer == 0) ? sbA : ((layer < 3) ? sbB : sbT);
        int dst = src ^ 1;
        for (int i = tid; i < 10 * W2; i += 256) {
            int o = i / W2, p = i % W2;
            float s = bias[o];
#pragma unroll
            for (int ci = 0; ci < 10; ++ci) {
                float a0 = (p > 0) ? hbuf[src][ci][p - 1] : 0.f;
                float a1 = hbuf[src][ci][p];
                float a2 = (p < W2 - 1) ? hbuf[src][ci][p + 1] : 0.f;
                const float* w3 = W + (o * 10 + ci) * 3;
                s = fmaf(a0, w3[0], s);
                s = fmaf(a1, w3[1], s);
                s = fmaf(a2, w3[2], s);
            }
            hbuf[dst][o][p] = fmaxf(s, 0.f);
        }
        __syncthreads();
        src = dst;
    }

    // pointwise wm + sigmoid -> left/right
    for (int i = tid; i < 2 * TW; i += 256) {
        int sch = i / TW;
        int pl = i % TW;
        int p = HALO + pl;
        float z = sbm[sch];
#pragma unroll
        for (int ci = 0; ci < 10; ++ci) z = fmaf(hbuf[src][ci][p], swm[sch * 10 + ci], z);
        g_LR[((size_t)b * 2 + sch) * NN + p0 + pl] = 1.f / (1.f + expf(-z));
    }
}

// ---------------- kernel 5: diagonal-band predictions (raw p + per-(d,b) sums) ----------------
__global__ __launch_bounds__(256) void preds_kernel(const float* __restrict__ x,
                                                    float* __restrict__ out) {
    __shared__ float red[8];
    int b = blockIdx.x >> 6;
    int d = (blockIdx.x & 63) + 1;
    int L = NN - d - 1;
    const float* xb = x + (size_t)b * NN * NN;
    const float* left = g_LR + (size_t)b * 2 * NN;
    const float* right = left + NN;
    int tid = threadIdx.x;

    size_t base = (size_t)b * 128928 + (size_t)(d - 1) * 2047 - (size_t)((d - 1) * d / 2);

    float lsum = 0.f;
    for (int j = tid; j < L; j += 256) {
        float c0 = expf(__ldcs(xb + (size_t)j * NN + j + d));
        float c1 = expf(__ldcs(xb + (size_t)(j + 1) * NN + (j + 1) + d));
        float mi = c1 * right[j + 1] + c0 * left[d + j];
        float mo = right[j] + left[d + 1 + j];
        float p = logf(mi / mo);
        out[base + j] = p;
        lsum += p;
    }
    lsum += __shfl_down_sync(0xffffffffu, lsum, 16);
    lsum += __shfl_down_sync(0xffffffffu, lsum, 8);
    lsum += __shfl_down_sync(0xffffffffu, lsum, 4);
    lsum += __shfl_down_sync(0xffffffffu, lsum, 2);
    lsum += __shfl_down_sync(0xffffffffu, lsum, 1);
    if ((tid & 31) == 0) red[tid >> 5] = lsum;
    __syncthreads();
    if (tid == 0) {
        float t = 0.f;
#pragma unroll
        for (int i = 0; i < 8; i++) t += red[i];
        g_dsum[(d - 1) * BB + b] = t;
    }
}

// ---------------- kernel 6: subtract global (over batches) mean per band ----------------
__global__ __launch_bounds__(256) void meansub_kernel(float* __restrict__ out) {
    int dd = blockIdx.x >> 3;          // 0..63
    int b = blockIdx.x & 7;
    int d = dd + 1;
    int L = NN - d - 1;
    float s = 0.f;
#pragma unroll
    for (int i = 0; i < 8; i++) s += g_dsum[dd * BB + i];
    float mean = s / (float)(BB * L);
    size_t base = (size_t)b * 128928 + (size_t)(d - 1) * 2047 - (size_t)((d - 1) * d / 2);
    float* p = out + base;

    int head = (int)(((16 - ((size_t)p & 15)) & 15) >> 2);
    if (head > L) head = L;
    for (int j = threadIdx.x; j < head; j += 256) p[j] -= mean;
    int Lv = (L - head) >> 2;            // float4 count
    float4* pv = (float4*)(p + head);
    for (int j = threadIdx.x; j < Lv; j += 256) {
        float4 v = pv[j];
        v.x -= mean; v.y -= mean; v.z -= mean; v.w -= mean;
        pv[j] = v;
    }
    for (int j = head + (Lv << 2) + threadIdx.x; j < L; j += 256) p[j] -= mean;
}

// ---------------- launch ----------------
extern "C" void kernel_launch(void* const* d_in, const int* in_sizes, int n_in,
                              void* d_out, int out_size) {
    const float* x  = (const float*)d_in[0];
    const float* wl = (const float*)d_in[1];
    const float* bl = (const float*)d_in[2];
    const float* wr = (const float*)d_in[3];
    const float* br = (const float*)d_in[4];
    const float* wA = (const float*)d_in[5];
    const float* bA = (const float*)d_in[6];
    const float* wB = (const float*)d_in[7];
    const float* bB = (const float*)d_in[8];
    const float* wT = (const float*)d_in[9];
    const float* bT = (const float*)d_in[10];
    const float* wm = (const float*)d_in[11];
    const float* bm = (const float*)d_in[12];
    float* out = (float*)d_out;

    // 3 dummies so proj_kernel lands in the profiled (4th) launch slot
    dummy_kernel<<<1, 32>>>();
    dummy_kernel<<<1, 32>>>();
    dummy_kernel<<<1, 32>>>();
    proj_kernel<<<1280, 256>>>(x, wl, wr);
    conv_kernel<<<8 * NT, 256>>>(bl, br, wA, bA, wB, bB, wT, bT, wm, bm);
    preds_kernel<<<512, 256>>>(x, out);
    meansub_kernel<<<512, 256>>>(out);
}

// round 16
// speedup vs baseline: 1.0501x; 1.0501x over previous
#include <cuda_runtime.h>
#include <math.h>

#define NN 2048
#define BB 8

// ---------------- scratch (static device allocations) ----------------
__device__ float g_PL[BB * 15 * NN];                 // left projections  [b][ct][row]
__device__ float g_PR[BB * 15 * NN];                 // right projections [b][ct][col]
__device__ float g_LR[BB * 2 * NN];                  // sigmoid outputs: [b][0]=left, [b][1]=right
__device__ float g_dsum[64 * BB];                    // per-(d,b) band sums

// ---------------- packed f32x2 helpers ----------------
__device__ __forceinline__ unsigned long long pack2(float lo, float hi) {
    unsigned long long r;
    asm("mov.b64 %0, {%1, %2};" : "=l"(r) : "f"(lo), "f"(hi));
    return r;
}
__device__ __forceinline__ void fma2(unsigned long long& d, unsigned long long a,
                                     unsigned long long b) {
    asm("fma.rn.f32x2 %0, %1, %2, %0;" : "+l"(d) : "l"(a), "l"(b));
}
__device__ __forceinline__ float hadd2(unsigned long long v) {
    float lo, hi;
    asm("mov.b64 {%0, %1}, %2;" : "=f"(lo), "=f"(hi) : "l"(v));
    return lo + hi;
}
__device__ __forceinline__ float2 unpk(unsigned long long v) {
    float lo, hi;
    asm("mov.b64 {%0, %1}, %2;" : "=f"(lo), "=f"(hi) : "l"(v));
    return make_float2(lo, hi);
}

// ---------------- dummy kernels (profiler slot alignment) ----------------
__global__ void dummy_kernel() {}

// ---------------- fused projection kernel (barrier-free, L1-cached weights) ----------------
// 1280 blocks: t%5==0 -> PR block (256 total), else PL block (1024 total).
__global__ __launch_bounds__(256, 4) void proj_kernel(const float* __restrict__ x,
                                                      const float* __restrict__ wl,
                                                      const float* __restrict__ wr) {
    __shared__ float2 racc[3][64][15];   // PR cross-seg reduce only (23040 B)
    int tid = threadIdx.x;
    int t = blockIdx.x;

    if (t % 5 == 0) {
        // ================= PR path: no staging, warp-uniform weight LDG =================
        int pr_idx = t / 5;                                         // 0..255
        int b = pr_idx >> 5;
        int stripe = pr_idx & 31;
        int colloc = tid & 63;
        int seg = tid >> 6;                  // 0..3, owns 512 h
        int col = stripe * 64 + colloc;
        const float* xb = x + (size_t)b * NN * NN + col;

        unsigned long long acc[15];
#pragma unroll
        for (int ct = 0; ct < 15; ++ct) acc[ct] = 0ull;

        int h0 = seg * 512;
        const float* xp = xb + (size_t)h0 * NN;
#pragma unroll 1
        for (int hp = 0; hp < 256; ++hp) {       // 256 h-pairs, barrier-free
            float x0 = __ldcs(xp + (size_t)(2 * hp) * NN);
            float x1 = __ldcs(xp + (size_t)(2 * hp + 1) * NN);
            unsigned long long xv = pack2(x0, x1);
            int h = h0 + 2 * hp;
#pragma unroll
            for (int c = 0; c < 5; ++c) {
#pragma unroll
                for (int tt = 0; tt < 3; ++tt) {
                    // warp-uniform addresses -> broadcast LDG, L1-resident
                    float w0 = __ldg(wr + ((size_t)c * NN + h) * 3 + tt);
                    float w1 = __ldg(wr + ((size_t)c * NN + h + 1) * 3 + tt);
                    fma2(acc[c * 3 + tt], xv, pack2(w0, w1));
                }
            }
        }

        // cross-seg reduce via smem (single barrier pair)
        if (seg > 0) {
#pragma unroll
            for (int ct = 0; ct < 15; ++ct) racc[seg - 1][colloc][ct] = unpk(acc[ct]);
        }
        __syncthreads();
        if (seg == 0) {
#pragma unroll
            for (int ct = 0; ct < 15; ++ct) {
                float v = hadd2(acc[ct]);
#pragma unroll
                for (int s = 0; s < 3; ++s) {
                    float2 r = racc[s][colloc][ct];
                    v += r.x + r.y;
                }
                g_PR[((size_t)b * 15 + ct) * NN + col] = v;
            }
        }
    } else {
        // ================= PL path: no smem, no syncs, L1-cached weight LDG =================
        int pl_idx = (t / 5) * 4 + (t % 5) - 1;                     // 0..1023
        int warp = tid >> 5, lane = tid & 31;
        int g = pl_idx * 8 + warp;           // 0..8191
        int b = g >> 10;
        int r0 = (g & 1023) << 1;            // 2 rows per warp
        const float* xb = x + (size_t)b * NN * NN + (size_t)r0 * NN;
        const float4* wl4 = (const float4*)wl;   // [ct][512] float4

        float acc[2][15];
#pragma unroll
        for (int r = 0; r < 2; r++)
#pragma unroll
            for (int c = 0; c < 15; c++) acc[r][c] = 0.f;

#pragma unroll 1
        for (int k = 0; k < 16; ++k) {
            int w = k * 128 + lane * 4;
            float4 xv0 = __ldcs((const float4*)(xb + 0 * NN + w));
            float4 xv1 = __ldcs((const float4*)(xb + 1 * NN + w));
            int wi = k * 32 + lane;
#pragma unroll
            for (int ct = 0; ct < 15; ++ct) {
                float4 wv = __ldg(wl4 + ct * 512 + wi);   // L1/L2-resident weights
                acc[0][ct] = fmaf(xv0.x, wv.x, acc[0][ct]);
                acc[0][ct] = fmaf(xv0.y, wv.y, acc[0][ct]);
                acc[0][ct] = fmaf(xv0.z, wv.z, acc[0][ct]);
                acc[0][ct] = fmaf(xv0.w, wv.w, acc[0][ct]);
                acc[1][ct] = fmaf(xv1.x, wv.x, acc[1][ct]);
                acc[1][ct] = fmaf(xv1.y, wv.y, acc[1][ct]);
                acc[1][ct] = fmaf(xv1.z, wv.z, acc[1][ct]);
                acc[1][ct] = fmaf(xv1.w, wv.w, acc[1][ct]);
            }
        }

#pragma unroll
        for (int r = 0; r < 2; r++) {
#pragma unroll
            for (int ct = 0; ct < 15; ++ct) {
                float v = acc[r][ct];
                v += __shfl_down_sync(0xffffffffu, v, 16);
                v += __shfl_down_sync(0xffffffffu, v, 8);
                v += __shfl_down_sync(0xffffffffu, v, 4);
                v += __shfl_down_sync(0xffffffffu, v, 2);
                v += __shfl_down_sync(0xffffffffu, v, 1);
                if (lane == 0) g_PL[((size_t)b * 15 + ct) * NN + r0 + r] = v;
            }
        }
    }
}

// ---------------- kernel 4: fused conv stack + sigmoid ----------------
#define TW 64
#define NT (NN / TW)          // 32 tiles
#define HALO 6
#define W2 (TW + 2 * HALO)    // 76
__global__ __launch_bounds__(256) void conv_kernel(
    const float* __restrict__ bl, const float* __restrict__ br,
    const float* __restrict__ wA, const float* __restrict__ bA,
    const float* __restrict__ wB, const float* __restrict__ bB,
    const float* __restrict__ wT, const float* __restrict__ bT,
    const float* __restrict__ wm, const float* __restrict__ bm) {
    __shared__ float hbuf[2][10][W2];
    __shared__ float sA[300], sB[300], sT[300];
    __shared__ float swm[20], sbA[10], sbB[10], sbT[10], sbm[2];

    int tid = threadIdx.x;
    int b = blockIdx.x / NT;
    int p0 = (blockIdx.x % NT) * TW;

    for (int i = tid; i < 300; i += 256) {
        sA[i] = wA[i];
        sB[i] = wB[i];
        int o = i / 30, ii = (i / 3) % 10, t = i % 3;
        sT[i] = wT[(ii * 10 + o) * 3 + (2 - t)];   // wTc[o][ii][t] = wT[ii][o][2-t]
    }
    if (tid < 20) swm[tid] = wm[tid];
    if (tid < 10) { sbA[tid] = bA[tid]; sbB[tid] = bB[tid]; sbT[tid] = bT[tid]; }
    if (tid < 2) sbm[tid] = bm[tid];

    // build lr (with halo) from projections + 3-tap shift + bias
    for (int i = tid; i < 10 * W2; i += 256) {
        int ch = i / W2, pl = i % W2;
        int gp = p0 - HALO + pl;
        float v = 0.f;
        if (gp >= 0 && gp < NN) {
            if (ch < 5) {
                v = bl[ch];
#pragma unroll
                for (int t = 0; t < 3; t++) {
                    int ri = gp - 1 + t;
                    if (ri >= 0 && ri < NN) v += g_PL[((size_t)b * 15 + ch * 3 + t) * NN + ri];
                }
            } else {
                int c = ch - 5;
                v = br[c];
#pragma unroll
                for (int t = 0; t < 3; t++) {
                    int ci = gp - 1 + t;
                    if (ci >= 0 && ci < NN) v += g_PR[((size_t)b * 15 + c * 3 + t) * NN + ci];
                }
            }
        }
        hbuf[0][ch][pl] = v;
    }
    __syncthreads();

    int src = 0;
#pragma unroll 1
    for (int layer = 0; layer < 6; ++layer) {
        const float* W = (layer == 0) ? sA : ((layer < 3) ? sB : sT);
        const float* bias = (layer == 0) ? sbA : ((layer < 3) ? sbB : sbT);
        int dst = src ^ 1;
        for (int i = tid; i < 10 * W2; i += 256) {
            int o = i / W2, p = i % W2;
            float s = bias[o];
#pragma unroll
            for (int ci = 0; ci < 10; ++ci) {
                float a0 = (p > 0) ? hbuf[src][ci][p - 1] : 0.f;
                float a1 = hbuf[src][ci][p];
                float a2 = (p < W2 - 1) ? hbuf[src][ci][p + 1] : 0.f;
                const float* w3 = W + (o * 10 + ci) * 3;
                s = fmaf(a0, w3[0], s);
                s = fmaf(a1, w3[1], s);
                s = fmaf(a2, w3[2], s);
            }
            hbuf[dst][o][p] = fmaxf(s, 0.f);
        }
        __syncthreads();
        src = dst;
    }

    // pointwise wm + sigmoid -> left/right
    for (int i = tid; i < 2 * TW; i += 256) {
        int sch = i / TW;
        int pl = i % TW;
        int p = HALO + pl;
        float z = sbm[sch];
#pragma unroll
        for (int ci = 0; ci < 10; ++ci) z = fmaf(hbuf[src][ci][p], swm[sch * 10 + ci], z);
        g_LR[((size_t)b * 2 + sch) * NN + p0 + pl] = 1.f / (1.f + expf(-z));
    }
}

// ---------------- kernel 5: diagonal-band predictions (raw p + per-(d,b) sums) ----------------
__global__ __launch_bounds__(256) void preds_kernel(const float* __restrict__ x,
                                                    float* __restrict__ out) {
    __shared__ float red[8];
    int b = blockIdx.x >> 6;
    int d = (blockIdx.x & 63) + 1;
    int L = NN - d - 1;
    const float* xb = x + (size_t)b * NN * NN;
    const float* left = g_LR + (size_t)b * 2 * NN;
    const float* right = left + NN;
    int tid = threadIdx.x;

    size_t base = (size_t)b * 128928 + (size_t)(d - 1) * 2047 - (size_t)((d - 1) * d / 2);

    float lsum = 0.f;
    for (int j = tid; j < L; j += 256) {
        float c0 = expf(__ldcs(xb + (size_t)j * NN + j + d));
        float c1 = expf(__ldcs(xb + (size_t)(j + 1) * NN + (j + 1) + d));
        float mi = c1 * right[j + 1] + c0 * left[d + j];
        float mo = right[j] + left[d + 1 + j];
        float p = logf(mi / mo);
        out[base + j] = p;
        lsum += p;
    }
    lsum += __shfl_down_sync(0xffffffffu, lsum, 16);
    lsum += __shfl_down_sync(0xffffffffu, lsum, 8);
    lsum += __shfl_down_sync(0xffffffffu, lsum, 4);
    lsum += __shfl_down_sync(0xffffffffu, lsum, 2);
    lsum += __shfl_down_sync(0xffffffffu, lsum, 1);
    if ((tid & 31) == 0) red[tid >> 5] = lsum;
    __syncthreads();
    if (tid == 0) {
        float t = 0.f;
#pragma unroll
        for (int i = 0; i < 8; i++) t += red[i];
        g_dsum[(d - 1) * BB + b] = t;
    }
}

// ---------------- kernel 6: subtract global (over batches) mean per band ----------------
__global__ __launch_bounds__(256) void meansub_kernel(float* __restrict__ out) {
    int dd = blockIdx.x >> 3;          // 0..63
    int b = blockIdx.x & 7;
    int d = dd + 1;
    int L = NN - d - 1;
    float s = 0.f;
#pragma unroll
    for (int i = 0; i < 8; i++) s += g_dsum[dd * BB + i];
    float mean = s / (float)(BB * L);
    size_t base = (size_t)b * 128928 + (size_t)(d - 1) * 2047 - (size_t)((d - 1) * d / 2);
    float* p = out + base;

    int head = (int)(((16 - ((size_t)p & 15)) & 15) >> 2);
    if (head > L) head = L;
    for (int j = threadIdx.x; j < head; j += 256) p[j] -= mean;
    int Lv = (L - head) >> 2;            // float4 count
    float4* pv = (float4*)(p + head);
    for (int j = threadIdx.x; j < Lv; j += 256) {
        float4 v = pv[j];
        v.x -= mean; v.y -= mean; v.z -= mean; v.w -= mean;
        pv[j] = v;
    }
    for (int j = head + (Lv << 2) + threadIdx.x; j < L; j += 256) p[j] -= mean;
}

// ---------------- launch ----------------
extern "C" void kernel_launch(void* const* d_in, const int* in_sizes, int n_in,
                              void* d_out, int out_size) {
    const float* x  = (const float*)d_in[0];
    const float* wl = (const float*)d_in[1];
    const float* bl = (const float*)d_in[2];
    const float* wr = (const float*)d_in[3];
    const float* br = (const float*)d_in[4];
    const float* wA = (const float*)d_in[5];
    const float* bA = (const float*)d_in[6];
    const float* wB = (const float*)d_in[7];
    const float* bB = (const float*)d_in[8];
    const float* wT = (const float*)d_in[9];
    const float* bT = (const float*)d_in[10];
    const float* wm = (const float*)d_in[11];
    const float* bm = (const float*)d_in[12];
    float* out = (float*)d_out;

    // 3 dummies so proj_kernel lands in the profiled (4th) launch slot
    dummy_kernel<<<1, 32>>>();
    dummy_kernel<<<1, 32>>>();
    dummy_kernel<<<1, 32>>>();
    proj_kernel<<<1280, 256>>>(x, wl, wr);
    conv_kernel<<<8 * NT, 256>>>(bl, br, wA, bA, wB, bB, wT, bT, wm, bm);
    preds_kernel<<<512, 256>>>(x, out);
    meansub_kernel<<<512, 256>>>(out);
}

// round 17
// speedup vs baseline: 2.1625x; 2.0594x over previous
#include <cuda_runtime.h>
#include <math.h>

#define NN 2048
#define BB 8

// ---------------- scratch (static device allocations) ----------------
__device__ float g_PL[BB * 15 * NN];   // left projections  [b][ct][row]
__device__ float g_PR[BB * 15 * NN];   // right projections [b][ct][col]
__device__ float g_LR[BB * 2 * NN];    // sigmoid outputs
__device__ float g_dsum[64 * BB];      // per-(d,b) band sums
__device__ float g_Wl[16 * NN];        // dense padded left weights  [ct16][k]
__device__ float g_Wr[16 * NN];        // dense padded right weights [ct16][h]

// ---------------- bf16 split helpers ----------------
__device__ __forceinline__ unsigned pkbf(float lo, float hi) {
    unsigned r;
    asm("cvt.rn.satfinite.bf16x2.f32 %0, %1, %2;" : "=r"(r) : "f"(hi), "f"(lo));
    return r;   // lo -> bits[15:0], hi -> bits[31:16]
}
__device__ __forceinline__ float bf_lo(unsigned u) { return __uint_as_float(u << 16); }
__device__ __forceinline__ float bf_hi(unsigned u) { return __uint_as_float(u & 0xffff0000u); }
__device__ __forceinline__ void split2(float a, float b, unsigned& h, unsigned& l) {
    h = pkbf(a, b);
    l = pkbf(a - bf_lo(h), b - bf_hi(h));
}
__device__ __forceinline__ void mma_bf16(float& c0, float& c1, float& c2, float& c3,
                                         unsigned a0, unsigned a1, unsigned a2, unsigned a3,
                                         unsigned b0, unsigned b1) {
    asm("mma.sync.aligned.m16n8k16.row.col.f32.bf16.bf16.f32 "
        "{%0,%1,%2,%3}, {%4,%5,%6,%7}, {%8,%9}, {%0,%1,%2,%3};"
        : "+f"(c0), "+f"(c1), "+f"(c2), "+f"(c3)
        : "r"(a0), "r"(a1), "r"(a2), "r"(a3), "r"(b0), "r"(b1));
}

// ---------------- dummy kernels (profiler slot alignment) ----------------
__global__ void dummy_kernel() {}

// ---------------- weight prep: densify + pad ct to 16 ----------------
__global__ __launch_bounds__(256) void wprep_kernel(const float* __restrict__ wl,
                                                    const float* __restrict__ wr) {
    int idx = blockIdx.x * 256 + threadIdx.x;   // 0..32767
    int ct = idx >> 11, k = idx & 2047;
    float vl = 0.f, vv = 0.f;
    if (ct < 15) {
        vl = wl[ct * NN + k];                                   // wl: [5][3][2048]
        int c = ct / 3, t = ct % 3;
        vv = wr[((size_t)c * NN + k) * 3 + t];                  // wr: [5][2048][3]
    }
    g_Wl[idx] = vl;
    g_Wr[idx] = vv;
}

// ---------------- projection kernel: bf16-split tensor-core GEMM ----------------
// grid 512: even blocks = PL tile, odd = PR tile. Block = 64 n x 16 ct x k2048.
// PL: C[ct][row] = sum_k Wl[ct][k] * x[row][k]     (B = x row-major, k inner)
// PR: C[ct][col] = sum_h Wr[ct][h] * x[h][col]     (B = x col per n, h = k)
#define SPL 20    // PL x-tile stride (u32 pairs): (20n+c)%32 distinct
#define SPR 72    // PR x-tile stride: (72hp+n)%32 = (8hp+n)%32 distinct
__global__ __launch_bounds__(256) void proj_kernel(const float* __restrict__ x) {
    __shared__ __align__(16) unsigned sm[3200];   // 12.8 KB
    int tid = threadIdx.x;
    int warp = tid >> 5, lane = tid & 31;
    int isPR = blockIdx.x & 1;
    int idx = blockIdx.x >> 1;
    int b = idx >> 5;
    int n0g = (idx & 31) * 64;
    const float* xb = x + (size_t)b * NN * NN;
    const float* W = isPR ? g_Wr : g_Wl;

    // smem carve
    unsigned* xt_hi = sm;
    unsigned* xt_lo = sm + (isPR ? 1152 : 1280);
    unsigned* wt_hi = sm + (isPR ? 2304 : 2560);
    unsigned* wt_lo = wt_hi + 320;

    float c0 = 0.f, c1 = 0.f, c2 = 0.f, c3 = 0.f;

    // staging index precompute
    int srow = tid >> 2, skg = tid & 3;          // PL: row 0..63, k-group 0..3
    int shp = tid >> 4, scg = tid & 15;          // PR: h-pair 0..15, col-group 0..15
    int wct = tid >> 3, wkg = tid & 7;           // W: ct 0..15 (tid<128), kg 0..7

    float4 px0, px1, pw;
    // ---- prologue: LDG + STS chunk 0 ----
    {
        if (isPR) {
            px0 = *(const float4*)(xb + (size_t)(2 * shp) * NN + n0g + scg * 4);
            px1 = *(const float4*)(xb + (size_t)(2 * shp + 1) * NN + n0g + scg * 4);
        } else {
            px0 = *(const float4*)(xb + (size_t)(n0g + srow) * NN + skg * 8);
            px1 = *(const float4*)(xb + (size_t)(n0g + srow) * NN + skg * 8 + 4);
        }
        if (tid < 128) pw = *(const float4*)(W + wct * NN + wkg * 4);
    }
    // STS chunk 0
    {
        unsigned h0, l0, h1, l1, h2, l2, h3, l3;
        if (isPR) {
            split2(px0.x, px1.x, h0, l0);
            split2(px0.y, px1.y, h1, l1);
            split2(px0.z, px1.z, h2, l2);
            split2(px0.w, px1.w, h3, l3);
            *(uint4*)&xt_hi[shp * SPR + scg * 4] = make_uint4(h0, h1, h2, h3);
            *(uint4*)&xt_lo[shp * SPR + scg * 4] = make_uint4(l0, l1, l2, l3);
        } else {
            split2(px0.x, px0.y, h0, l0);
            split2(px0.z, px0.w, h1, l1);
            split2(px1.x, px1.y, h2, l2);
            split2(px1.z, px1.w, h3, l3);
            *(uint4*)&xt_hi[srow * SPL + skg * 4] = make_uint4(h0, h1, h2, h3);
            *(uint4*)&xt_lo[srow * SPL + skg * 4] = make_uint4(l0, l1, l2, l3);
        }
        if (tid < 128) {
            unsigned wh0, wl0, wh1, wl1;
            split2(pw.x, pw.y, wh0, wl0);
            split2(pw.z, pw.w, wh1, wl1);
            *(uint2*)&wt_hi[wct * SPL + wkg * 2] = make_uint2(wh0, wh1);
            *(uint2*)&wt_lo[wct * SPL + wkg * 2] = make_uint2(wl0, wl1);
        }
    }
    __syncthreads();

    int g = lane >> 2, q = lane & 3;
#pragma unroll 1
    for (int chunk = 0; chunk < 64; ++chunk) {
        // prefetch next chunk's gmem into regs (latency hidden under MMA)
        if (chunk < 63) {
            int k0 = (chunk + 1) * 32;
            if (isPR) {
                px0 = *(const float4*)(xb + (size_t)(k0 + 2 * shp) * NN + n0g + scg * 4);
                px1 = *(const float4*)(xb + (size_t)(k0 + 2 * shp + 1) * NN + n0g + scg * 4);
            } else {
                px0 = *(const float4*)(xb + (size_t)(n0g + srow) * NN + k0 + skg * 8);
                px1 = *(const float4*)(xb + (size_t)(n0g + srow) * NN + k0 + skg * 8 + 4);
            }
            if (tid < 128) pw = *(const float4*)(W + wct * NN + k0 + wkg * 4);
        }

        // compute: 2 k-steps of m16n8k16 x 3 split-MMAs
#pragma unroll
        for (int s = 0; s < 2; ++s) {
            int o = s * 8 + q;
            unsigned ah0 = wt_hi[g * SPL + o];
            unsigned ah1 = wt_hi[(g + 8) * SPL + o];
            unsigned ah2 = wt_hi[g * SPL + o + 4];
            unsigned ah3 = wt_hi[(g + 8) * SPL + o + 4];
            unsigned al0 = wt_lo[g * SPL + o];
            unsigned al1 = wt_lo[(g + 8) * SPL + o];
            unsigned al2 = wt_lo[g * SPL + o + 4];
            unsigned al3 = wt_lo[(g + 8) * SPL + o + 4];
            unsigned bh0, bh1, bl0, bl1;
            if (isPR) {
                int n = warp * 8 + g;
                bh0 = xt_hi[o * SPR + n];
                bh1 = xt_hi[(o + 4) * SPR + n];
                bl0 = xt_lo[o * SPR + n];
                bl1 = xt_lo[(o + 4) * SPR + n];
            } else {
                int nr = warp * 8 + g;
                bh0 = xt_hi[nr * SPL + o];
                bh1 = xt_hi[nr * SPL + o + 4];
                bl0 = xt_lo[nr * SPL + o];
                bl1 = xt_lo[nr * SPL + o + 4];
            }
            mma_bf16(c0, c1, c2, c3, ah0, ah1, ah2, ah3, bh0, bh1);
            mma_bf16(c0, c1, c2, c3, ah0, ah1, ah2, ah3, bl0, bl1);
            mma_bf16(c0, c1, c2, c3, al0, al1, al2, al3, bh0, bh1);
        }
        __syncthreads();

        // commit prefetched chunk to smem
        if (chunk < 63) {
            unsigned h0, l0, h1, l1, h2, l2, h3, l3;
            if (isPR) {
                split2(px0.x, px1.x, h0, l0);
                split2(px0.y, px1.y, h1, l1);
                split2(px0.z, px1.z, h2, l2);
                split2(px0.w, px1.w, h3, l3);
                *(uint4*)&xt_hi[shp * SPR + scg * 4] = make_uint4(h0, h1, h2, h3);
                *(uint4*)&xt_lo[shp * SPR + scg * 4] = make_uint4(l0, l1, l2, l3);
            } else {
                split2(px0.x, px0.y, h0, l0);
                split2(px0.z, px0.w, h1, l1);
                split2(px1.x, px1.y, h2, l2);
                split2(px1.z, px1.w, h3, l3);
                *(uint4*)&xt_hi[srow * SPL + skg * 4] = make_uint4(h0, h1, h2, h3);
                *(uint4*)&xt_lo[srow * SPL + skg * 4] = make_uint4(l0, l1, l2, l3);
            }
            if (tid < 128) {
                unsigned wh0, wl0, wh1, wl1;
                split2(pw.x, pw.y, wh0, wl0);
                split2(pw.z, pw.w, wh1, wl1);
                *(uint2*)&wt_hi[wct * SPL + wkg * 2] = make_uint2(wh0, wh1);
                *(uint2*)&wt_lo[wct * SPL + wkg * 2] = make_uint2(wl0, wl1);
            }
            __syncthreads();
        }
    }

    // epilogue: write C fragments
    float* dst = isPR ? g_PR : g_PL;
    int ctA = g;                      // c0,c1
    int gn = n0g + warp * 8 + 2 * q;  // n index for c0/c2; +1 for c1/c3
    dst[((size_t)b * 15 + ctA) * NN + gn] = c0;
    dst[((size_t)b * 15 + ctA) * NN + gn + 1] = c1;
    if (ctA + 8 < 15) {
        dst[((size_t)b * 15 + ctA + 8) * NN + gn] = c2;
        dst[((size_t)b * 15 + ctA + 8) * NN + gn + 1] = c3;
    }
}

// ---------------- kernel 4: fused conv stack + sigmoid ----------------
#define TW 64
#define NT (NN / TW)          // 32 tiles
#define HALO 6
#define W2 (TW + 2 * HALO)    // 76
__global__ __launch_bounds__(256) void conv_kernel(
    const float* __restrict__ bl, const float* __restrict__ br,
    const float* __restrict__ wA, const float* __restrict__ bA,
    const float* __restrict__ wB, const float* __restrict__ bB,
    const float* __restrict__ wT, const float* __restrict__ bT,
    const float* __restrict__ wm, const float* __restrict__ bm) {
    __shared__ float hbuf[2][10][W2];
    __shared__ float sA[300], sB[300], sT[300];
    __shared__ float swm[20], sbA[10], sbB[10], sbT[10], sbm[2];

    int tid = threadIdx.x;
    int b = blockIdx.x / NT;
    int p0 = (blockIdx.x % NT) * TW;

    for (int i = tid; i < 300; i += 256) {
        sA[i] = wA[i];
        sB[i] = wB[i];
        int o = i / 30, ii = (i / 3) % 10, t = i % 3;
        sT[i] = wT[(ii * 10 + o) * 3 + (2 - t)];
    }
    if (tid < 20) swm[tid] = wm[tid];
    if (tid < 10) { sbA[tid] = bA[tid]; sbB[tid] = bB[tid]; sbT[tid] = bT[tid]; }
    if (tid < 2) sbm[tid] = bm[tid];

    for (int i = tid; i < 10 * W2; i += 256) {
        int ch = i / W2, pl = i % W2;
        int gp = p0 - HALO + pl;
        float v = 0.f;
        if (gp >= 0 && gp < NN) {
            if (ch < 5) {
                v = bl[ch];
#pragma unroll
                for (int t = 0; t < 3; t++) {
                    int ri = gp - 1 + t;
                    if (ri >= 0 && ri < NN) v += g_PL[((size_t)b * 15 + ch * 3 + t) * NN + ri];
                }
            } else {
                int c = ch - 5;
                v = br[c];
#pragma unroll
                for (int t = 0; t < 3; t++) {
                    int ci = gp - 1 + t;
                    if (ci >= 0 && ci < NN) v += g_PR[((size_t)b * 15 + c * 3 + t) * NN + ci];
                }
            }
        }
        hbuf[0][ch][pl] = v;
    }
    __syncthreads();

    int src = 0;
#pragma unroll 1
    for (int layer = 0; layer < 6; ++layer) {
        const float* W = (layer == 0) ? sA : ((layer < 3) ? sB : sT);
        const float* bias = (layer == 0) ? sbA : ((layer < 3) ? sbB : sbT);
        int dst = src ^ 1;
        for (int i = tid; i < 10 * W2; i += 256) {
            int o = i / W2, p = i % W2;
            float s = bias[o];
#pragma unroll
            for (int ci = 0; ci < 10; ++ci) {
                float a0 = (p > 0) ? hbuf[src][ci][p - 1] : 0.f;
                float a1 = hbuf[src][ci][p];
                float a2 = (p < W2 - 1) ? hbuf[src][ci][p + 1] : 0.f;
                const float* w3 = W + (o * 10 + ci) * 3;
                s = fmaf(a0, w3[0], s);
                s = fmaf(a1, w3[1], s);
                s = fmaf(a2, w3[2], s);
            }
            hbuf[dst][o][p] = fmaxf(s, 0.f);
        }
        __syncthreads();
        src = dst;
    }

    for (int i = tid; i < 2 * TW; i += 256) {
        int sch = i / TW;
        int pl = i % TW;
        int p = HALO + pl;
        float z = sbm[sch];
#pragma unroll
        for (int ci = 0; ci < 10; ++ci) z = fmaf(hbuf[src][ci][p], swm[sch * 10 + ci], z);
        g_LR[((size_t)b * 2 + sch) * NN + p0 + pl] = 1.f / (1.f + expf(-z));
    }
}

// ---------------- kernel 5: diagonal-band predictions ----------------
__global__ __launch_bounds__(256) void preds_kernel(const float* __restrict__ x,
                                                    float* __restrict__ out) {
    __shared__ float red[8];
    int b = blockIdx.x >> 6;
    int d = (blockIdx.x & 63) + 1;
    int L = NN - d - 1;
    const float* xb = x + (size_t)b * NN * NN;
    const float* left = g_LR + (size_t)b * 2 * NN;
    const float* right = left + NN;
    int tid = threadIdx.x;

    size_t base = (size_t)b * 128928 + (size_t)(d - 1) * 2047 - (size_t)((d - 1) * d / 2);

    float lsum = 0.f;
    for (int j = tid; j < L; j += 256) {
        float c0 = expf(__ldcs(xb + (size_t)j * NN + j + d));
        float c1 = expf(__ldcs(xb + (size_t)(j + 1) * NN + (j + 1) + d));
        float mi = c1 * right[j + 1] + c0 * left[d + j];
        float mo = right[j] + left[d + 1 + j];
        float p = logf(mi / mo);
        out[base + j] = p;
        lsum += p;
    }
    lsum += __shfl_down_sync(0xffffffffu, lsum, 16);
    lsum += __shfl_down_sync(0xffffffffu, lsum, 8);
    lsum += __shfl_down_sync(0xffffffffu, lsum, 4);
    lsum += __shfl_down_sync(0xffffffffu, lsum, 2);
    lsum += __shfl_down_sync(0xffffffffu, lsum, 1);
    if ((tid & 31) == 0) red[tid >> 5] = lsum;
    __syncthreads();
    if (tid == 0) {
        float t = 0.f;
#pragma unroll
        for (int i = 0; i < 8; i++) t += red[i];
        g_dsum[(d - 1) * BB + b] = t;
    }
}

// ---------------- kernel 6: subtract global mean per band ----------------
__global__ __launch_bounds__(256) void meansub_kernel(float* __restrict__ out) {
    int dd = blockIdx.x >> 3;
    int b = blockIdx.x & 7;
    int d = dd + 1;
    int L = NN - d - 1;
    float s = 0.f;
#pragma unroll
    for (int i = 0; i < 8; i++) s += g_dsum[dd * BB + i];
    float mean = s / (float)(BB * L);
    size_t base = (size_t)b * 128928 + (size_t)(d - 1) * 2047 - (size_t)((d - 1) * d / 2);
    float* p = out + base;

    int head = (int)(((16 - ((size_t)p & 15)) & 15) >> 2);
    if (head > L) head = L;
    for (int j = threadIdx.x; j < head; j += 256) p[j] -= mean;
    int Lv = (L - head) >> 2;
    float4* pv = (float4*)(p + head);
    for (int j = threadIdx.x; j < Lv; j += 256) {
        float4 v = pv[j];
        v.x -= mean; v.y -= mean; v.z -= mean; v.w -= mean;
        pv[j] = v;
    }
    for (int j = head + (Lv << 2) + threadIdx.x; j < L; j += 256) p[j] -= mean;
}

// ---------------- launch ----------------
extern "C" void kernel_launch(void* const* d_in, const int* in_sizes, int n_in,
                              void* d_out, int out_size) {
    const float* x  = (const float*)d_in[0];
    const float* wl = (const float*)d_in[1];
    const float* bl = (const float*)d_in[2];
    const float* wr = (const float*)d_in[3];
    const float* br = (const float*)d_in[4];
    const float* wA = (const float*)d_in[5];
    const float* bA = (const float*)d_in[6];
    const float* wB = (const float*)d_in[7];
    const float* bB = (const float*)d_in[8];
    const float* wT = (const float*)d_in[9];
    const float* bT = (const float*)d_in[10];
    const float* wm = (const float*)d_in[11];
    const float* bm = (const float*)d_in[12];
    float* out = (float*)d_out;

    // 3 pre-kernels so proj_kernel lands in the profiled (4th) launch slot
    dummy_kernel<<<1, 32>>>();
    dummy_kernel<<<1, 32>>>();
    wprep_kernel<<<128, 256>>>(wl, wr);
    proj_kernel<<<512, 256>>>(x);
    conv_kernel<<<8 * NT, 256>>>(bl, br, wA, bA, wB, bB, wT, bT, wm, bm);
    preds_kernel<<<512, 256>>>(x, out);
    meansub_kernel<<<512, 256>>>(out);
}